// round 1
// baseline (speedup 1.0000x reference)
#include <cuda_runtime.h>
#include <math.h>

#define SEQ    2048
#define BATCH  4
#define KCTX   3
#define EMBED  512
#define HIDDEN 256
#define VOCAB  32000
#define MROWS  (SEQ * BATCH)      // 8192
#define K1     (KCTX * EMBED)     // 1536

// Scratch (static device globals — no allocation in kernel_launch)
__device__ float g_flat[MROWS * K1];     // 50.3 MB gathered contexts
__device__ float g_h[MROWS * HIDDEN];    // 8.4 MB hidden activations

// ---------------------------------------------------------------------------
// Gather: flat[r, g*512+e] = emb[tok(s-2+g, b), e], token 0 for pos < 0
// ---------------------------------------------------------------------------
__global__ void gather_kernel(const int* __restrict__ tokens,
                              const float* __restrict__ emb) {
    int idx = blockIdx.x * blockDim.x + threadIdx.x;  // one float4
    const int Q = K1 / 4;                              // 384 float4 per row
    int total = MROWS * Q;
    if (idx >= total) return;
    int r = idx / Q;
    int q = idx - r * Q;
    int s = r / BATCH;
    int b = r - s * BATCH;
    int g = q / (EMBED / 4);
    int e4 = q - g * (EMBED / 4);
    int pos = s + g - (KCTX - 1);
    int tok = (pos >= 0) ? tokens[pos * BATCH + b] : 0;
    float4 v = reinterpret_cast<const float4*>(emb + (size_t)tok * EMBED)[e4];
    reinterpret_cast<float4*>(g_flat)[idx] = v;
}

// ---------------------------------------------------------------------------
// SGEMM: C[M,N] = A[M,K] @ B[K,N] + bias, optional exact GELU.
// Block tile 128x128, BK=16, 256 threads, 8x8 per thread (4+4 split rows/cols).
// All dims assumed to divide the tile sizes exactly.
// ---------------------------------------------------------------------------
__device__ __forceinline__ float gelu_exact(float x) {
    return 0.5f * x * (1.0f + erff(x * 0.70710678118654752f));
}

template <bool DO_GELU>
__global__ void __launch_bounds__(256)
sgemm128(const float* __restrict__ A, const float* __restrict__ B,
         const float* __restrict__ bias, float* __restrict__ C,
         int N, int Kdim) {
    const int BM = 128, BN = 128, BK = 16;
    __shared__ float As[BK][BM];
    __shared__ float Bs[BK][BN];

    int tid = threadIdx.x;
    int tx = tid & 15;         // 0..15 -> column groups
    int ty = tid >> 4;         // 0..15 -> row groups
    int bm = blockIdx.y * BM;
    int bn = blockIdx.x * BN;

    const float* Ab = A + (size_t)bm * Kdim;
    const float* Bb = B + bn;

    float acc[8][8];
#pragma unroll
    for (int i = 0; i < 8; i++)
#pragma unroll
        for (int j = 0; j < 8; j++) acc[i][j] = 0.0f;

    for (int k0 = 0; k0 < Kdim; k0 += BK) {
        // Load A tile (128 rows x 16 k) transposed into As
#pragma unroll
        for (int i = 0; i < 2; i++) {
            int lin = tid + i * 256;        // 0..511 float4 slots
            int row = lin >> 2;
            int c4  = (lin & 3) * 4;
            float4 v = *reinterpret_cast<const float4*>(
                Ab + (size_t)row * Kdim + k0 + c4);
            As[c4 + 0][row] = v.x;
            As[c4 + 1][row] = v.y;
            As[c4 + 2][row] = v.z;
            As[c4 + 3][row] = v.w;
        }
        // Load B tile (16 k x 128 n) directly
#pragma unroll
        for (int i = 0; i < 2; i++) {
            int lin = tid + i * 256;
            int row = lin >> 5;             // /32
            int c4  = (lin & 31) * 4;
            *reinterpret_cast<float4*>(&Bs[row][c4]) =
                *reinterpret_cast<const float4*>(Bb + (size_t)(k0 + row) * N + c4);
        }
        __syncthreads();

#pragma unroll
        for (int k = 0; k < BK; k++) {
            float4 a0 = *reinterpret_cast<float4*>(&As[k][ty * 4]);
            float4 a1 = *reinterpret_cast<float4*>(&As[k][ty * 4 + 64]);
            float4 b0 = *reinterpret_cast<float4*>(&Bs[k][tx * 4]);
            float4 b1 = *reinterpret_cast<float4*>(&Bs[k][tx * 4 + 64]);
            float a[8] = {a0.x, a0.y, a0.z, a0.w, a1.x, a1.y, a1.z, a1.w};
            float b[8] = {b0.x, b0.y, b0.z, b0.w, b1.x, b1.y, b1.z, b1.w};
#pragma unroll
            for (int i = 0; i < 8; i++)
#pragma unroll
                for (int j = 0; j < 8; j++) acc[i][j] += a[i] * b[j];
        }
        __syncthreads();
    }

    // Epilogue: bias (+ GELU), vectorized stores
    float bv[8];
#pragma unroll
    for (int j = 0; j < 4; j++) {
        bv[j]     = bias[bn + tx * 4 + j];
        bv[j + 4] = bias[bn + tx * 4 + 64 + j];
    }

#pragma unroll
    for (int ri = 0; ri < 8; ri++) {
        int row = (ri < 4) ? (ty * 4 + ri) : (ty * 4 + 64 + ri - 4);
        float* Crow = C + (size_t)(bm + row) * N + bn;
        float4 o0, o1;
        float v;
        v = acc[ri][0] + bv[0]; o0.x = DO_GELU ? gelu_exact(v) : v;
        v = acc[ri][1] + bv[1]; o0.y = DO_GELU ? gelu_exact(v) : v;
        v = acc[ri][2] + bv[2]; o0.z = DO_GELU ? gelu_exact(v) : v;
        v = acc[ri][3] + bv[3]; o0.w = DO_GELU ? gelu_exact(v) : v;
        v = acc[ri][4] + bv[4]; o1.x = DO_GELU ? gelu_exact(v) : v;
        v = acc[ri][5] + bv[5]; o1.y = DO_GELU ? gelu_exact(v) : v;
        v = acc[ri][6] + bv[6]; o1.z = DO_GELU ? gelu_exact(v) : v;
        v = acc[ri][7] + bv[7]; o1.w = DO_GELU ? gelu_exact(v) : v;
        *reinterpret_cast<float4*>(Crow + tx * 4)      = o0;
        *reinterpret_cast<float4*>(Crow + tx * 4 + 64) = o1;
    }
}

// ---------------------------------------------------------------------------
// kernel_launch
// Inputs (metadata order): tokens_seq(int32), emb, W1, b1, W2, b2 (fp32)
// Output: logits fp32 (2048, 4, 32000)
// ---------------------------------------------------------------------------
extern "C" void kernel_launch(void* const* d_in, const int* in_sizes, int n_in,
                              void* d_out, int out_size) {
    const int*   tokens = (const int*)  d_in[0];
    const float* emb    = (const float*)d_in[1];
    const float* W1     = (const float*)d_in[2];
    const float* b1     = (const float*)d_in[3];
    const float* W2     = (const float*)d_in[4];
    const float* b2     = (const float*)d_in[5];
    float* out = (float*)d_out;

    float* flat_p = nullptr;
    float* h_p    = nullptr;
    cudaGetSymbolAddress((void**)&flat_p, g_flat);
    cudaGetSymbolAddress((void**)&h_p,    g_h);

    // 1) Gather contexts -> g_flat
    {
        int total4 = MROWS * (K1 / 4);
        int threads = 256;
        int blocks = (total4 + threads - 1) / threads;
        gather_kernel<<<blocks, threads>>>(tokens, emb);
    }

    // 2) h = GELU(flat @ W1 + b1) : M=8192, N=256, K=1536
    {
        dim3 grid(HIDDEN / 128, MROWS / 128);
        sgemm128<true><<<grid, 256>>>(flat_p, W1, b1, h_p, HIDDEN, K1);
    }

    // 3) logits = h @ W2 + b2 : M=8192, N=32000, K=256
    {
        dim3 grid(VOCAB / 128, MROWS / 128);
        sgemm128<false><<<grid, 256>>>(h_p, W2, b2, out, VOCAB, HIDDEN);
    }
}

// round 3
// speedup vs baseline: 1.6041x; 1.6041x over previous
#include <cuda_runtime.h>
#include <cuda_bf16.h>
#include <math.h>
#include <stdint.h>

#define SEQ    2048
#define BATCH  4
#define KCTX   3
#define EMBED  512
#define HIDDEN 256
#define VOCAB  32000
#define MROWS  (SEQ * BATCH)      // 8192
#define K1     (KCTX * EMBED)     // 1536

// ---------------- scratch (static device globals) ----------------
__device__ __nv_bfloat16 g_flat_hi[MROWS * K1];
__device__ __nv_bfloat16 g_flat_lo[MROWS * K1];
__device__ __nv_bfloat16 g_w1t_hi[HIDDEN * K1];     // [256][1536] K-major
__device__ __nv_bfloat16 g_w1t_lo[HIDDEN * K1];
__device__ __nv_bfloat16 g_w2t_hi[VOCAB * HIDDEN];  // [32000][256] K-major
__device__ __nv_bfloat16 g_w2t_lo[VOCAB * HIDDEN];
__device__ __nv_bfloat16 g_h_hi[MROWS * HIDDEN];
__device__ __nv_bfloat16 g_h_lo[MROWS * HIDDEN];

// ---------------- helpers ----------------
__device__ __forceinline__ uint32_t smem_u32(const void* p) {
    uint32_t a;
    asm("{ .reg .u64 t; cvta.to.shared.u64 t, %1; cvt.u32.u64 %0, t; }" : "=r"(a) : "l"(p));
    return a;
}
__device__ __forceinline__ void cp16(uint32_t dst, const void* src) {
    asm volatile("cp.async.cg.shared.global [%0], [%1], 16;\n" :: "r"(dst), "l"(src));
}
__device__ __forceinline__ void cp_commit() { asm volatile("cp.async.commit_group;\n" ::: "memory"); }

#define LDSM_X4(r0, r1, r2, r3, addr) \
    asm volatile("ldmatrix.sync.aligned.m8n8.x4.shared.b16 {%0,%1,%2,%3}, [%4];" \
                 : "=r"(r0), "=r"(r1), "=r"(r2), "=r"(r3) : "r"(addr))

#define MMA16816(d, a, b) \
    asm volatile("mma.sync.aligned.m16n8k16.row.col.f32.bf16.bf16.f32 " \
                 "{%0,%1,%2,%3}, {%4,%5,%6,%7}, {%8,%9}, {%0,%1,%2,%3};" \
                 : "+f"((d)[0]), "+f"((d)[1]), "+f"((d)[2]), "+f"((d)[3]) \
                 : "r"((a)[0]), "r"((a)[1]), "r"((a)[2]), "r"((a)[3]), \
                   "r"((b)[0]), "r"((b)[1]))

__device__ __forceinline__ void bsplit(float x, __nv_bfloat16& hi, __nv_bfloat16& lo) {
    hi = __float2bfloat16(x);
    lo = __float2bfloat16(x - __bfloat162float(hi));
}
__device__ __forceinline__ float gelu_exact(float x) {
    return 0.5f * x * (1.0f + erff(x * 0.70710678118654752f));
}

// ---------------------------------------------------------------------------
// Gather + split: flat[r, g*512+e] = emb[tok, e] -> bf16 hi/lo
// ---------------------------------------------------------------------------
__global__ void gather_split(const int* __restrict__ tokens, const float* __restrict__ emb) {
    int idx = blockIdx.x * blockDim.x + threadIdx.x;  // one float4
    const int Q = K1 / 4;
    if (idx >= MROWS * Q) return;
    int r = idx / Q;
    int q = idx - r * Q;
    int s = r >> 2;
    int b = r & 3;
    int g = q / (EMBED / 4);
    int e4 = q - g * (EMBED / 4);
    int pos = s + g - (KCTX - 1);
    int tok = (pos >= 0) ? tokens[pos * BATCH + b] : 0;
    float4 v = reinterpret_cast<const float4*>(emb + (size_t)tok * EMBED)[e4];
    size_t off = (size_t)r * K1 + g * EMBED + e4 * 4;
    __nv_bfloat16 h0, h1, h2, h3, l0, l1, l2, l3;
    bsplit(v.x, h0, l0); bsplit(v.y, h1, l1); bsplit(v.z, h2, l2); bsplit(v.w, h3, l3);
    *reinterpret_cast<__nv_bfloat162*>(g_flat_hi + off)     = __nv_bfloat162(h0, h1);
    *reinterpret_cast<__nv_bfloat162*>(g_flat_hi + off + 2) = __nv_bfloat162(h2, h3);
    *reinterpret_cast<__nv_bfloat162*>(g_flat_lo + off)     = __nv_bfloat162(l0, l1);
    *reinterpret_cast<__nv_bfloat162*>(g_flat_lo + off + 2) = __nv_bfloat162(l2, l3);
}

// ---------------------------------------------------------------------------
// Transpose + split: W[R][C] -> T[C][R] bf16 hi/lo
// ---------------------------------------------------------------------------
__global__ void transpose_split(const float* __restrict__ W,
                                __nv_bfloat16* __restrict__ Thi,
                                __nv_bfloat16* __restrict__ Tlo, int R, int C) {
    __shared__ float t[32][33];
    int c = blockIdx.x * 32 + threadIdx.x;
    int r = blockIdx.y * 32 + threadIdx.y;
    t[threadIdx.y][threadIdx.x] = W[(size_t)r * C + c];
    __syncthreads();
    int c2 = blockIdx.x * 32 + threadIdx.y;
    int r2 = blockIdx.y * 32 + threadIdx.x;
    float v = t[threadIdx.x][threadIdx.y];
    __nv_bfloat16 h, l;
    bsplit(v, h, l);
    Thi[(size_t)c2 * R + r2] = h;
    Tlo[(size_t)c2 * R + r2] = l;
}

// ---------------------------------------------------------------------------
// HMMA GEMM: C[M,N] = A[M,K] @ B[N,K]^T with bf16 hi/lo 3-term split,
// fp32 accumulate. BM=BN=128, BK=32, 8 warps (2x4), warp tile 64x32.
// 3-stage cp.async pipeline. K-loop runs 3 phases: (Ahi,Bhi),(Ahi,Blo),(Alo,Bhi).
// EPI=0: out = acc + bias -> fp32.  EPI=1: gelu(acc+bias) -> bf16 hi/lo.
// ---------------------------------------------------------------------------
#define NTH 256
#define RSB 80                       // smem row stride bytes (32 bf16 + 8 pad)
#define AB_BYTES (128 * RSB)         // 10240
#define STAGE_B  (2 * AB_BYTES)      // 20480
#define SMEM_BYTES (3 * STAGE_B)     // 61440

template <int KD, int EPI>
__global__ void __launch_bounds__(NTH, 1)
gemm_hmma(const __nv_bfloat16* __restrict__ Ahi, const __nv_bfloat16* __restrict__ Alo,
          const __nv_bfloat16* __restrict__ Bhi, const __nv_bfloat16* __restrict__ Blo,
          const float* __restrict__ bias,
          float* __restrict__ outf,
          __nv_bfloat16* __restrict__ outhi, __nv_bfloat16* __restrict__ outlo,
          int N) {
    extern __shared__ char smem[];
    constexpr int KPB = KD / 32;     // k-blocks per phase
    constexpr int NKB = 3 * KPB;     // total k-blocks
    uint32_t sb = smem_u32(smem);
    int tid = threadIdx.x;
    int wid = tid >> 5;
    int lane = tid & 31;
    int warp_m = wid & 1;            // 0..1
    int warp_n = wid >> 1;           // 0..3
    int bm = blockIdx.y * 128;
    int bn = blockIdx.x * 128;

    const __nv_bfloat16* Asel[3] = {Ahi, Ahi, Alo};
    const __nv_bfloat16* Bsel[3] = {Bhi, Blo, Bhi};

    float acc[4][4][4];
#pragma unroll
    for (int i = 0; i < 4; i++)
#pragma unroll
        for (int j = 0; j < 4; j++)
#pragma unroll
            for (int r = 0; r < 4; r++) acc[i][j][r] = 0.0f;

    // per-thread load slots: 2 A rows + 2 B rows (4 cp16 each iter pair)
    auto issue = [&](int kb) {
        int s = kb % 3;
        int phase = kb / KPB;
        int koff = (kb - phase * KPB) * 32;
        const __nv_bfloat16* Ap = Asel[phase];
        const __nv_bfloat16* Bp = Bsel[phase];
        uint32_t base = sb + s * STAGE_B;
#pragma unroll
        for (int i = 0; i < 2; i++) {
            int li = tid + i * NTH;          // 0..511
            int r = li >> 2;
            int ch = li & 3;
            cp16(base + r * RSB + ch * 16,
                 Ap + (size_t)(bm + r) * KD + koff + ch * 8);
            cp16(base + AB_BYTES + r * RSB + ch * 16,
                 Bp + (size_t)(bn + r) * KD + koff + ch * 8);
        }
        cp_commit();
    };

    issue(0);
    issue(1);

    // ldmatrix per-lane address components
    int lrow = (lane & 7) + ((lane >> 3) & 1) * 8;   // row within 16-row group
    int lkb = (lane >> 4) * 16;                      // 0 or 16 bytes (k half)
    uint32_t a_off = (uint32_t)(warp_m * 64 + lrow) * RSB + lkb;
    uint32_t b_off = (uint32_t)(warp_n * 32 + lrow) * RSB + lkb;

    for (int kb = 0; kb < NKB; kb++) {
        int s = kb % 3;
        asm volatile("cp.async.wait_group 1;\n" ::: "memory");
        __syncthreads();
        if (kb + 2 < NKB) issue(kb + 2);

        uint32_t smA = sb + s * STAGE_B;
        uint32_t smB = smA + AB_BYTES;
#pragma unroll
        for (int k16 = 0; k16 < 2; k16++) {
            uint32_t ar[4][4];
#pragma unroll
            for (int fm = 0; fm < 4; fm++)
                LDSM_X4(ar[fm][0], ar[fm][1], ar[fm][2], ar[fm][3],
                        smA + a_off + fm * 16 * RSB + k16 * 32);
            uint32_t br[4][2];
#pragma unroll
            for (int fp = 0; fp < 2; fp++) {
                uint32_t r0, r1, r2, r3;
                LDSM_X4(r0, r1, r2, r3, smB + b_off + fp * 16 * RSB + k16 * 32);
                br[2 * fp][0] = r0; br[2 * fp][1] = r2;
                br[2 * fp + 1][0] = r1; br[2 * fp + 1][1] = r3;
            }
#pragma unroll
            for (int fm = 0; fm < 4; fm++)
#pragma unroll
                for (int fn = 0; fn < 4; fn++)
                    MMA16816(acc[fm][fn], ar[fm], br[fn]);
        }
    }

    // ---------------- epilogue ----------------
    int gr = lane >> 2;
    int qc = (lane & 3) * 2;
#pragma unroll
    for (int fm = 0; fm < 4; fm++) {
        int m0 = bm + warp_m * 64 + fm * 16 + gr;
#pragma unroll
        for (int fn = 0; fn < 4; fn++) {
            int c0 = bn + warp_n * 32 + fn * 8 + qc;
            float bv0 = __ldg(bias + c0);
            float bv1 = __ldg(bias + c0 + 1);
            float v00 = acc[fm][fn][0] + bv0;
            float v01 = acc[fm][fn][1] + bv1;
            float v10 = acc[fm][fn][2] + bv0;
            float v11 = acc[fm][fn][3] + bv1;
            if (EPI == 0) {
                float2 a = make_float2(v00, v01);
                float2 b = make_float2(v10, v11);
                *reinterpret_cast<float2*>(outf + (size_t)m0 * N + c0) = a;
                *reinterpret_cast<float2*>(outf + (size_t)(m0 + 8) * N + c0) = b;
            } else {
                float g00 = gelu_exact(v00), g01 = gelu_exact(v01);
                float g10 = gelu_exact(v10), g11 = gelu_exact(v11);
                __nv_bfloat16 h, l;
                __nv_bfloat162 hh0, ll0, hh1, ll1;
                bsplit(g00, h, l); hh0.x = h; ll0.x = l;
                bsplit(g01, h, l); hh0.y = h; ll0.y = l;
                bsplit(g10, h, l); hh1.x = h; ll1.x = l;
                bsplit(g11, h, l); hh1.y = h; ll1.y = l;
                *reinterpret_cast<__nv_bfloat162*>(outhi + (size_t)m0 * N + c0) = hh0;
                *reinterpret_cast<__nv_bfloat162*>(outlo + (size_t)m0 * N + c0) = ll0;
                *reinterpret_cast<__nv_bfloat162*>(outhi + (size_t)(m0 + 8) * N + c0) = hh1;
                *reinterpret_cast<__nv_bfloat162*>(outlo + (size_t)(m0 + 8) * N + c0) = ll1;
            }
        }
    }
}

// ---------------------------------------------------------------------------
extern "C" void kernel_launch(void* const* d_in, const int* in_sizes, int n_in,
                              void* d_out, int out_size) {
    const int*   tokens = (const int*)  d_in[0];
    const float* emb    = (const float*)d_in[1];
    const float* W1     = (const float*)d_in[2];
    const float* b1     = (const float*)d_in[3];
    const float* W2     = (const float*)d_in[4];
    const float* b2     = (const float*)d_in[5];
    float* out = (float*)d_out;

    __nv_bfloat16 *fh, *fl, *w1h, *w1l, *w2h, *w2l, *hh, *hl;
    cudaGetSymbolAddress((void**)&fh,  g_flat_hi);
    cudaGetSymbolAddress((void**)&fl,  g_flat_lo);
    cudaGetSymbolAddress((void**)&w1h, g_w1t_hi);
    cudaGetSymbolAddress((void**)&w1l, g_w1t_lo);
    cudaGetSymbolAddress((void**)&w2h, g_w2t_hi);
    cudaGetSymbolAddress((void**)&w2l, g_w2t_lo);
    cudaGetSymbolAddress((void**)&hh,  g_h_hi);
    cudaGetSymbolAddress((void**)&hl,  g_h_lo);

    cudaFuncSetAttribute(gemm_hmma<K1, 1>,
                         cudaFuncAttributeMaxDynamicSharedMemorySize, SMEM_BYTES);
    cudaFuncSetAttribute(gemm_hmma<HIDDEN, 0>,
                         cudaFuncAttributeMaxDynamicSharedMemorySize, SMEM_BYTES);

    // 1) gather + split
    {
        int total4 = MROWS * (K1 / 4);
        gather_split<<<(total4 + 255) / 256, 256>>>(tokens, emb);
    }
    // 2) weight transposes + splits
    {
        dim3 blk(32, 32);
        transpose_split<<<dim3(HIDDEN / 32, K1 / 32), blk>>>(W1, w1h, w1l, K1, HIDDEN);
        transpose_split<<<dim3(VOCAB / 32, HIDDEN / 32), blk>>>(W2, w2h, w2l, HIDDEN, VOCAB);
    }
    // 3) h = GELU(flat @ W1 + b1) -> bf16 hi/lo   (M=8192, N=256, K=1536)
    {
        dim3 grid(HIDDEN / 128, MROWS / 128);   // (2, 64)
        gemm_hmma<K1, 1><<<grid, NTH, SMEM_BYTES>>>(fh, fl, w1h, w1l, b1,
                                                    nullptr, hh, hl, HIDDEN);
    }
    // 4) logits = h @ W2 + b2   (M=8192, N=32000, K=256)
    {
        dim3 grid(VOCAB / 128, MROWS / 128);    // (250, 64)
        gemm_hmma<HIDDEN, 0><<<grid, NTH, SMEM_BYTES>>>(hh, hl, w2h, w2l, b2,
                                                        out, nullptr, nullptr, VOCAB);
    }
}

// round 4
// speedup vs baseline: 1.8183x; 1.1336x over previous
#include <cuda_runtime.h>
#include <cuda_bf16.h>
#include <math.h>
#include <stdint.h>

#define SEQ    2048
#define BATCH  4
#define KCTX   3
#define EMBED  512
#define HIDDEN 256
#define VOCAB  32000
#define MROWS  (SEQ * BATCH)      // 8192
#define K1     (KCTX * EMBED)     // 1536

// ---------------- scratch (static device globals) ----------------
__device__ __nv_bfloat16 g_flat_hi[MROWS * K1];
__device__ __nv_bfloat16 g_flat_lo[MROWS * K1];
__device__ __nv_bfloat16 g_w1t_hi[HIDDEN * K1];     // [256][1536] K-major
__device__ __nv_bfloat16 g_w1t_lo[HIDDEN * K1];
__device__ __nv_bfloat16 g_w2t_hi[VOCAB * HIDDEN];  // [32000][256] K-major
__device__ __nv_bfloat16 g_w2t_lo[VOCAB * HIDDEN];
__device__ __nv_bfloat16 g_h_hi[MROWS * HIDDEN];
__device__ __nv_bfloat16 g_h_lo[MROWS * HIDDEN];

// ---------------- helpers ----------------
__device__ __forceinline__ uint32_t smem_u32(const void* p) {
    uint32_t a;
    asm("{ .reg .u64 t; cvta.to.shared.u64 t, %1; cvt.u32.u64 %0, t; }" : "=r"(a) : "l"(p));
    return a;
}
__device__ __forceinline__ void cp16(uint32_t dst, const void* src) {
    asm volatile("cp.async.cg.shared.global [%0], [%1], 16;\n" :: "r"(dst), "l"(src));
}
__device__ __forceinline__ void cp_commit() { asm volatile("cp.async.commit_group;\n" ::: "memory"); }

#define LDSM_X4(r0, r1, r2, r3, addr) \
    asm volatile("ldmatrix.sync.aligned.m8n8.x4.shared.b16 {%0,%1,%2,%3}, [%4];" \
                 : "=r"(r0), "=r"(r1), "=r"(r2), "=r"(r3) : "r"(addr))

#define MMA16816(d, a, b) \
    asm volatile("mma.sync.aligned.m16n8k16.row.col.f32.bf16.bf16.f32 " \
                 "{%0,%1,%2,%3}, {%4,%5,%6,%7}, {%8,%9}, {%0,%1,%2,%3};" \
                 : "+f"((d)[0]), "+f"((d)[1]), "+f"((d)[2]), "+f"((d)[3]) \
                 : "r"((a)[0]), "r"((a)[1]), "r"((a)[2]), "r"((a)[3]), \
                   "r"((b)[0]), "r"((b)[1]))

__device__ __forceinline__ void bsplit(float x, __nv_bfloat16& hi, __nv_bfloat16& lo) {
    hi = __float2bfloat16(x);
    lo = __float2bfloat16(x - __bfloat162float(hi));
}
__device__ __forceinline__ float gelu_exact(float x) {
    return 0.5f * x * (1.0f + erff(x * 0.70710678118654752f));
}

// ---------------------------------------------------------------------------
// Gather + split
// ---------------------------------------------------------------------------
__global__ void gather_split(const int* __restrict__ tokens, const float* __restrict__ emb) {
    int idx = blockIdx.x * blockDim.x + threadIdx.x;  // one float4
    const int Q = K1 / 4;
    if (idx >= MROWS * Q) return;
    int r = idx / Q;
    int q = idx - r * Q;
    int s = r >> 2;
    int b = r & 3;
    int g = q / (EMBED / 4);
    int e4 = q - g * (EMBED / 4);
    int pos = s + g - (KCTX - 1);
    int tok = (pos >= 0) ? tokens[pos * BATCH + b] : 0;
    float4 v = reinterpret_cast<const float4*>(emb + (size_t)tok * EMBED)[e4];
    size_t off = (size_t)r * K1 + g * EMBED + e4 * 4;
    __nv_bfloat16 h0, h1, h2, h3, l0, l1, l2, l3;
    bsplit(v.x, h0, l0); bsplit(v.y, h1, l1); bsplit(v.z, h2, l2); bsplit(v.w, h3, l3);
    *reinterpret_cast<__nv_bfloat162*>(g_flat_hi + off)     = __nv_bfloat162(h0, h1);
    *reinterpret_cast<__nv_bfloat162*>(g_flat_hi + off + 2) = __nv_bfloat162(h2, h3);
    *reinterpret_cast<__nv_bfloat162*>(g_flat_lo + off)     = __nv_bfloat162(l0, l1);
    *reinterpret_cast<__nv_bfloat162*>(g_flat_lo + off + 2) = __nv_bfloat162(l2, l3);
}

// ---------------------------------------------------------------------------
// Transpose + split: W[R][C] -> T[C][R] bf16 hi/lo
// ---------------------------------------------------------------------------
__global__ void transpose_split(const float* __restrict__ W,
                                __nv_bfloat16* __restrict__ Thi,
                                __nv_bfloat16* __restrict__ Tlo, int R, int C) {
    __shared__ float t[32][33];
    int c = blockIdx.x * 32 + threadIdx.x;
    int r = blockIdx.y * 32 + threadIdx.y;
    t[threadIdx.y][threadIdx.x] = W[(size_t)r * C + c];
    __syncthreads();
    int c2 = blockIdx.x * 32 + threadIdx.y;
    int r2 = blockIdx.y * 32 + threadIdx.x;
    float v = t[threadIdx.x][threadIdx.y];
    __nv_bfloat16 h, l;
    bsplit(v, h, l);
    Thi[(size_t)c2 * R + r2] = h;
    Tlo[(size_t)c2 * R + r2] = l;
}

// ---------------------------------------------------------------------------
// HMMA GEMM, fused 3-phase hi/lo split per k-block.
// BM=128, BN template (128 or 256), BK=32. 8 warps = 2(m) x 4(n).
// Warp tile 64 x (BN/4). Each smem stage holds Ahi,Alo,Bhi,Blo for one
// k-block; one sync services all 3 MMA phases.
// EPI=0: out = acc + bias -> fp32.  EPI=1: gelu(acc+bias) -> bf16 hi/lo.
// ---------------------------------------------------------------------------
#define NTH 256
#define RSB 80   // 32 bf16 (64B) + 16B pad

template <int KD, int BN_, int EPI>
__global__ void __launch_bounds__(NTH, 1)
gemm_hmma(const __nv_bfloat16* __restrict__ Ahi, const __nv_bfloat16* __restrict__ Alo,
          const __nv_bfloat16* __restrict__ Bhi, const __nv_bfloat16* __restrict__ Blo,
          const float* __restrict__ bias,
          float* __restrict__ outf,
          __nv_bfloat16* __restrict__ outhi, __nv_bfloat16* __restrict__ outlo,
          int N) {
    extern __shared__ char smem[];
    constexpr int NKB = KD / 32;                 // k-blocks
    constexpr int NFR = BN_ / 32;                // n8 frags per warp (4 or 8)
    constexpr int NLD = NFR / 2;                 // B ldsm.x4 per variant per k16
    constexpr int ROWS_STAGE = 256 + 2 * BN_;    // Ahi128+Alo128+Bhi+Blo rows
    constexpr int STAGE_B = ROWS_STAGE * RSB;
    constexpr int NI = ROWS_STAGE / 64;          // cp16 iters per thread
    constexpr uint32_t A_LO_OFF = 128 * RSB;
    constexpr uint32_t B_HI_OFF = 256 * RSB;
    constexpr uint32_t B_LO_OFF = (256 + BN_) * RSB;

    uint32_t sb = smem_u32(smem);
    int tid = threadIdx.x;
    int wid = tid >> 5;
    int lane = tid & 31;
    int warp_m = wid & 1;            // 0..1
    int warp_n = wid >> 1;           // 0..3
    int bm = blockIdx.y * 128;
    int bn = blockIdx.x * BN_;

    float acc[4][NFR][4];
#pragma unroll
    for (int i = 0; i < 4; i++)
#pragma unroll
        for (int j = 0; j < NFR; j++)
#pragma unroll
            for (int r = 0; r < 4; r++) acc[i][j][r] = 0.0f;

    auto issue = [&](int kb) {
        int s = kb % 3;
        int koff = kb * 32;
        uint32_t base = sb + s * STAGE_B;
#pragma unroll
        for (int i = 0; i < NI; i++) {
            int li = tid + i * NTH;
            int r = li >> 2;               // stage row 0..ROWS_STAGE-1
            int ch = li & 3;
            const __nv_bfloat16* src;
            if (i < 2)       src = Ahi + (size_t)(bm + r) * KD;
            else if (i < 4)  src = Alo + (size_t)(bm + r - 128) * KD;
            else if (i < 4 + BN_ / 64)
                             src = Bhi + (size_t)(bn + r - 256) * KD;
            else             src = Blo + (size_t)(bn + r - 256 - BN_) * KD;
            cp16(base + r * RSB + ch * 16, src + koff + ch * 8);
        }
        cp_commit();
    };

    issue(0);
    issue(1);

    int lrow = (lane & 7) + ((lane >> 3) & 1) * 8;
    int lkb = (lane >> 4) * 16;
    uint32_t a_off = (uint32_t)(warp_m * 64 + lrow) * RSB + lkb;
    uint32_t b_off = (uint32_t)(warp_n * (BN_ / 4) + lrow) * RSB + lkb;

    for (int kb = 0; kb < NKB; kb++) {
        int s = kb % 3;
        asm volatile("cp.async.wait_group 1;\n" ::: "memory");
        __syncthreads();
        if (kb + 2 < NKB) issue(kb + 2);

        uint32_t smA = sb + s * STAGE_B;
#pragma unroll
        for (int k16 = 0; k16 < 2; k16++) {
            uint32_t kb32 = k16 * 32;
            uint32_t ah[4][4], al[4][4];
#pragma unroll
            for (int fm = 0; fm < 4; fm++)
                LDSM_X4(ah[fm][0], ah[fm][1], ah[fm][2], ah[fm][3],
                        smA + a_off + fm * 16 * RSB + kb32);
#pragma unroll
            for (int fm = 0; fm < 4; fm++)
                LDSM_X4(al[fm][0], al[fm][1], al[fm][2], al[fm][3],
                        smA + A_LO_OFF + a_off + fm * 16 * RSB + kb32);

            uint32_t br[NFR][2];
            // phase: B hi  (Ahi*Bhi and Alo*Bhi)
#pragma unroll
            for (int fp = 0; fp < NLD; fp++) {
                uint32_t r0, r1, r2, r3;
                LDSM_X4(r0, r1, r2, r3,
                        smA + B_HI_OFF + b_off + fp * 16 * RSB + kb32);
                br[2 * fp][0] = r0; br[2 * fp][1] = r2;
                br[2 * fp + 1][0] = r1; br[2 * fp + 1][1] = r3;
            }
#pragma unroll
            for (int fm = 0; fm < 4; fm++)
#pragma unroll
                for (int fn = 0; fn < NFR; fn++)
                    MMA16816(acc[fm][fn], ah[fm], br[fn]);
#pragma unroll
            for (int fm = 0; fm < 4; fm++)
#pragma unroll
                for (int fn = 0; fn < NFR; fn++)
                    MMA16816(acc[fm][fn], al[fm], br[fn]);
            // phase: B lo  (Ahi*Blo), reuse br registers
#pragma unroll
            for (int fp = 0; fp < NLD; fp++) {
                uint32_t r0, r1, r2, r3;
                LDSM_X4(r0, r1, r2, r3,
                        smA + B_LO_OFF + b_off + fp * 16 * RSB + kb32);
                br[2 * fp][0] = r0; br[2 * fp][1] = r2;
                br[2 * fp + 1][0] = r1; br[2 * fp + 1][1] = r3;
            }
#pragma unroll
            for (int fm = 0; fm < 4; fm++)
#pragma unroll
                for (int fn = 0; fn < NFR; fn++)
                    MMA16816(acc[fm][fn], ah[fm], br[fn]);
        }
    }

    // ---------------- epilogue ----------------
    int gr = lane >> 2;
    int qc = (lane & 3) * 2;
#pragma unroll
    for (int fm = 0; fm < 4; fm++) {
        int m0 = bm + warp_m * 64 + fm * 16 + gr;
#pragma unroll
        for (int fn = 0; fn < NFR; fn++) {
            int c0 = bn + warp_n * (BN_ / 4) + fn * 8 + qc;
            float2 bv = *reinterpret_cast<const float2*>(bias + c0);
            float v00 = acc[fm][fn][0] + bv.x;
            float v01 = acc[fm][fn][1] + bv.y;
            float v10 = acc[fm][fn][2] + bv.x;
            float v11 = acc[fm][fn][3] + bv.y;
            if (EPI == 0) {
                *reinterpret_cast<float2*>(outf + (size_t)m0 * N + c0) =
                    make_float2(v00, v01);
                *reinterpret_cast<float2*>(outf + (size_t)(m0 + 8) * N + c0) =
                    make_float2(v10, v11);
            } else {
                float g00 = gelu_exact(v00), g01 = gelu_exact(v01);
                float g10 = gelu_exact(v10), g11 = gelu_exact(v11);
                __nv_bfloat16 h, l;
                __nv_bfloat162 hh0, ll0, hh1, ll1;
                bsplit(g00, h, l); hh0.x = h; ll0.x = l;
                bsplit(g01, h, l); hh0.y = h; ll0.y = l;
                bsplit(g10, h, l); hh1.x = h; ll1.x = l;
                bsplit(g11, h, l); hh1.y = h; ll1.y = l;
                *reinterpret_cast<__nv_bfloat162*>(outhi + (size_t)m0 * N + c0) = hh0;
                *reinterpret_cast<__nv_bfloat162*>(outlo + (size_t)m0 * N + c0) = ll0;
                *reinterpret_cast<__nv_bfloat162*>(outhi + (size_t)(m0 + 8) * N + c0) = hh1;
                *reinterpret_cast<__nv_bfloat162*>(outlo + (size_t)(m0 + 8) * N + c0) = ll1;
            }
        }
    }
}

// ---------------------------------------------------------------------------
extern "C" void kernel_launch(void* const* d_in, const int* in_sizes, int n_in,
                              void* d_out, int out_size) {
    const int*   tokens = (const int*)  d_in[0];
    const float* emb    = (const float*)d_in[1];
    const float* W1     = (const float*)d_in[2];
    const float* b1     = (const float*)d_in[3];
    const float* W2     = (const float*)d_in[4];
    const float* b2     = (const float*)d_in[5];
    float* out = (float*)d_out;

    __nv_bfloat16 *fh, *fl, *w1h, *w1l, *w2h, *w2l, *hh, *hl;
    cudaGetSymbolAddress((void**)&fh,  g_flat_hi);
    cudaGetSymbolAddress((void**)&fl,  g_flat_lo);
    cudaGetSymbolAddress((void**)&w1h, g_w1t_hi);
    cudaGetSymbolAddress((void**)&w1l, g_w1t_lo);
    cudaGetSymbolAddress((void**)&w2h, g_w2t_hi);
    cudaGetSymbolAddress((void**)&w2l, g_w2t_lo);
    cudaGetSymbolAddress((void**)&hh,  g_h_hi);
    cudaGetSymbolAddress((void**)&hl,  g_h_lo);

    constexpr int SMEM1 = 3 * (256 + 2 * 128) * RSB;   // BN=128: 122880
    constexpr int SMEM2 = 3 * (256 + 2 * 256) * RSB;   // BN=256: 184320
    cudaFuncSetAttribute(gemm_hmma<K1, 128, 1>,
                         cudaFuncAttributeMaxDynamicSharedMemorySize, SMEM1);
    cudaFuncSetAttribute(gemm_hmma<HIDDEN, 256, 0>,
                         cudaFuncAttributeMaxDynamicSharedMemorySize, SMEM2);

    // 1) gather + split
    {
        int total4 = MROWS * (K1 / 4);
        gather_split<<<(total4 + 255) / 256, 256>>>(tokens, emb);
    }
    // 2) weight transposes + splits
    {
        dim3 blk(32, 32);
        transpose_split<<<dim3(HIDDEN / 32, K1 / 32), blk>>>(W1, w1h, w1l, K1, HIDDEN);
        transpose_split<<<dim3(VOCAB / 32, HIDDEN / 32), blk>>>(W2, w2h, w2l, HIDDEN, VOCAB);
    }
    // 3) h = GELU(flat @ W1 + b1) -> bf16 hi/lo   (M=8192, N=256, K=1536)
    {
        dim3 grid(HIDDEN / 128, MROWS / 128);   // (2, 64)
        gemm_hmma<K1, 128, 1><<<grid, NTH, SMEM1>>>(fh, fl, w1h, w1l, b1,
                                                    nullptr, hh, hl, HIDDEN);
    }
    // 4) logits = h @ W2 + b2   (M=8192, N=32000, K=256)
    {
        dim3 grid(VOCAB / 256, MROWS / 128);    // (125, 64)
        gemm_hmma<HIDDEN, 256, 0><<<grid, NTH, SMEM2>>>(hh, hl, w2h, w2l, b2,
                                                        out, nullptr, nullptr, VOCAB);
    }
}

// round 5
// speedup vs baseline: 2.5399x; 1.3968x over previous
#include <cuda_runtime.h>
#include <cuda_bf16.h>
#include <math.h>
#include <stdint.h>

#define SEQ    2048
#define BATCH  4
#define KCTX   3
#define EMBED  512
#define HIDDEN 256
#define VOCAB  32000
#define MROWS  (SEQ * BATCH)      // 8192
#define K1     (KCTX * EMBED)     // 1536

// ---------------- scratch (static device globals) ----------------
__device__ __nv_bfloat16 g_flat_hi[MROWS * K1];
__device__ __nv_bfloat16 g_flat_lo[MROWS * K1];
__device__ __nv_bfloat16 g_w1t_hi[HIDDEN * K1];     // [256][1536] K-major
__device__ __nv_bfloat16 g_w1t_lo[HIDDEN * K1];
__device__ float         g_w2t[VOCAB * HIDDEN];     // [32000][256] K-major, tf32-rounded
__device__ float         g_h[MROWS * HIDDEN];       // [8192][256] tf32-rounded

// ---------------- helpers ----------------
__device__ __forceinline__ uint32_t smem_u32(const void* p) {
    uint32_t a;
    asm("{ .reg .u64 t; cvta.to.shared.u64 t, %1; cvt.u32.u64 %0, t; }" : "=r"(a) : "l"(p));
    return a;
}
__device__ __forceinline__ void cp16(uint32_t dst, const void* src) {
    asm volatile("cp.async.cg.shared.global [%0], [%1], 16;\n" :: "r"(dst), "l"(src));
}
__device__ __forceinline__ void cp_commit() { asm volatile("cp.async.commit_group;\n" ::: "memory"); }

#define LDSM_X4(r0, r1, r2, r3, addr) \
    asm volatile("ldmatrix.sync.aligned.m8n8.x4.shared.b16 {%0,%1,%2,%3}, [%4];" \
                 : "=r"(r0), "=r"(r1), "=r"(r2), "=r"(r3) : "r"(addr))

#define MMA16816(d, a, b) \
    asm volatile("mma.sync.aligned.m16n8k16.row.col.f32.bf16.bf16.f32 " \
                 "{%0,%1,%2,%3}, {%4,%5,%6,%7}, {%8,%9}, {%0,%1,%2,%3};" \
                 : "+f"((d)[0]), "+f"((d)[1]), "+f"((d)[2]), "+f"((d)[3]) \
                 : "r"((a)[0]), "r"((a)[1]), "r"((a)[2]), "r"((a)[3]), \
                   "r"((b)[0]), "r"((b)[1]))

#define MMATF32(d, a, b) \
    asm volatile("mma.sync.aligned.m16n8k8.row.col.f32.tf32.tf32.f32 " \
                 "{%0,%1,%2,%3}, {%4,%5,%6,%7}, {%8,%9}, {%0,%1,%2,%3};" \
                 : "+f"((d)[0]), "+f"((d)[1]), "+f"((d)[2]), "+f"((d)[3]) \
                 : "r"((a)[0]), "r"((a)[1]), "r"((a)[2]), "r"((a)[3]), \
                   "r"((b)[0]), "r"((b)[1]))

__device__ __forceinline__ uint32_t lds32(uint32_t addr) {
    uint32_t v;
    asm volatile("ld.shared.b32 %0, [%1];" : "=r"(v) : "r"(addr));
    return v;
}
__device__ __forceinline__ uint32_t tf32r(float x) {
    uint32_t u;
    asm("cvt.rna.tf32.f32 %0, %1;" : "=r"(u) : "f"(x));
    return u;
}
__device__ __forceinline__ void bsplit(float x, __nv_bfloat16& hi, __nv_bfloat16& lo) {
    hi = __float2bfloat16(x);
    lo = __float2bfloat16(x - __bfloat162float(hi));
}
__device__ __forceinline__ float gelu_exact(float x) {
    return 0.5f * x * (1.0f + erff(x * 0.70710678118654752f));
}

// ---------------------------------------------------------------------------
// Gather + split (bf16 hi/lo for GEMM1)
// ---------------------------------------------------------------------------
__global__ void gather_split(const int* __restrict__ tokens, const float* __restrict__ emb) {
    int idx = blockIdx.x * blockDim.x + threadIdx.x;  // one float4
    const int Q = K1 / 4;
    if (idx >= MROWS * Q) return;
    int r = idx / Q;
    int q = idx - r * Q;
    int s = r >> 2;
    int b = r & 3;
    int g = q / (EMBED / 4);
    int e4 = q - g * (EMBED / 4);
    int pos = s + g - (KCTX - 1);
    int tok = (pos >= 0) ? tokens[pos * BATCH + b] : 0;
    float4 v = reinterpret_cast<const float4*>(emb + (size_t)tok * EMBED)[e4];
    size_t off = (size_t)r * K1 + g * EMBED + e4 * 4;
    __nv_bfloat16 h0, h1, h2, h3, l0, l1, l2, l3;
    bsplit(v.x, h0, l0); bsplit(v.y, h1, l1); bsplit(v.z, h2, l2); bsplit(v.w, h3, l3);
    *reinterpret_cast<__nv_bfloat162*>(g_flat_hi + off)     = __nv_bfloat162(h0, h1);
    *reinterpret_cast<__nv_bfloat162*>(g_flat_hi + off + 2) = __nv_bfloat162(h2, h3);
    *reinterpret_cast<__nv_bfloat162*>(g_flat_lo + off)     = __nv_bfloat162(l0, l1);
    *reinterpret_cast<__nv_bfloat162*>(g_flat_lo + off + 2) = __nv_bfloat162(l2, l3);
}

// ---------------------------------------------------------------------------
// Transpose + split (bf16 hi/lo) for W1
// ---------------------------------------------------------------------------
__global__ void transpose_split(const float* __restrict__ W,
                                __nv_bfloat16* __restrict__ Thi,
                                __nv_bfloat16* __restrict__ Tlo, int R, int C) {
    __shared__ float t[32][33];
    int c = blockIdx.x * 32 + threadIdx.x;
    int r = blockIdx.y * 32 + threadIdx.y;
    t[threadIdx.y][threadIdx.x] = W[(size_t)r * C + c];
    __syncthreads();
    int c2 = blockIdx.x * 32 + threadIdx.y;
    int r2 = blockIdx.y * 32 + threadIdx.x;
    float v = t[threadIdx.x][threadIdx.y];
    __nv_bfloat16 h, l;
    bsplit(v, h, l);
    Thi[(size_t)c2 * R + r2] = h;
    Tlo[(size_t)c2 * R + r2] = l;
}

// ---------------------------------------------------------------------------
// Transpose + tf32 round for W2: W[R][C] -> T[C][R] (fp32, tf32-rounded)
// ---------------------------------------------------------------------------
__global__ void transpose_tf32(const float* __restrict__ W, float* __restrict__ T,
                               int R, int C) {
    __shared__ float t[32][33];
    int c = blockIdx.x * 32 + threadIdx.x;
    int r = blockIdx.y * 32 + threadIdx.y;
    t[threadIdx.y][threadIdx.x] = W[(size_t)r * C + c];
    __syncthreads();
    int c2 = blockIdx.x * 32 + threadIdx.y;
    int r2 = blockIdx.y * 32 + threadIdx.x;
    T[(size_t)c2 * R + r2] = __uint_as_float(tf32r(t[threadIdx.x][threadIdx.y]));
}

// ---------------------------------------------------------------------------
// GEMM1 (HMMA split-bf16, fused 3-phase): h = tf32(gelu(flat @ W1^T + b1))
// BM=128, BN=128, BK=32, 8 warps (2x4), warp tile 64x32.
// ---------------------------------------------------------------------------
#define NTH 256
#define RSB 80   // 32 bf16 (64B) + 16B pad

template <int KD, int BN_>
__global__ void __launch_bounds__(NTH, 1)
gemm_hmma(const __nv_bfloat16* __restrict__ Ahi, const __nv_bfloat16* __restrict__ Alo,
          const __nv_bfloat16* __restrict__ Bhi, const __nv_bfloat16* __restrict__ Blo,
          const float* __restrict__ bias, float* __restrict__ outf, int N) {
    extern __shared__ char smem[];
    constexpr int NKB = KD / 32;
    constexpr int NFR = BN_ / 32;
    constexpr int NLD = NFR / 2;
    constexpr int ROWS_STAGE = 256 + 2 * BN_;
    constexpr int STAGE_B = ROWS_STAGE * RSB;
    constexpr int NI = ROWS_STAGE / 64;
    constexpr uint32_t A_LO_OFF = 128 * RSB;
    constexpr uint32_t B_HI_OFF = 256 * RSB;
    constexpr uint32_t B_LO_OFF = (256 + BN_) * RSB;

    uint32_t sb = smem_u32(smem);
    int tid = threadIdx.x;
    int wid = tid >> 5;
    int lane = tid & 31;
    int warp_m = wid & 1;
    int warp_n = wid >> 1;
    int bm = blockIdx.y * 128;
    int bn = blockIdx.x * BN_;

    float acc[4][NFR][4];
#pragma unroll
    for (int i = 0; i < 4; i++)
#pragma unroll
        for (int j = 0; j < NFR; j++)
#pragma unroll
            for (int r = 0; r < 4; r++) acc[i][j][r] = 0.0f;

    auto issue = [&](int kb) {
        int s = kb % 3;
        int koff = kb * 32;
        uint32_t base = sb + s * STAGE_B;
#pragma unroll
        for (int i = 0; i < NI; i++) {
            int li = tid + i * NTH;
            int r = li >> 2;
            int ch = li & 3;
            const __nv_bfloat16* src;
            if (i < 2)       src = Ahi + (size_t)(bm + r) * KD;
            else if (i < 4)  src = Alo + (size_t)(bm + r - 128) * KD;
            else if (i < 4 + BN_ / 64)
                             src = Bhi + (size_t)(bn + r - 256) * KD;
            else             src = Blo + (size_t)(bn + r - 256 - BN_) * KD;
            cp16(base + r * RSB + ch * 16, src + koff + ch * 8);
        }
        cp_commit();
    };

    issue(0);
    issue(1);

    int lrow = (lane & 7) + ((lane >> 3) & 1) * 8;
    int lkb = (lane >> 4) * 16;
    uint32_t a_off = (uint32_t)(warp_m * 64 + lrow) * RSB + lkb;
    uint32_t b_off = (uint32_t)(warp_n * (BN_ / 4) + lrow) * RSB + lkb;

    for (int kb = 0; kb < NKB; kb++) {
        int s = kb % 3;
        asm volatile("cp.async.wait_group 1;\n" ::: "memory");
        __syncthreads();
        if (kb + 2 < NKB) issue(kb + 2);

        uint32_t smA = sb + s * STAGE_B;
#pragma unroll
        for (int k16 = 0; k16 < 2; k16++) {
            uint32_t kb32 = k16 * 32;
            uint32_t ah[4][4], al[4][4];
#pragma unroll
            for (int fm = 0; fm < 4; fm++)
                LDSM_X4(ah[fm][0], ah[fm][1], ah[fm][2], ah[fm][3],
                        smA + a_off + fm * 16 * RSB + kb32);
#pragma unroll
            for (int fm = 0; fm < 4; fm++)
                LDSM_X4(al[fm][0], al[fm][1], al[fm][2], al[fm][3],
                        smA + A_LO_OFF + a_off + fm * 16 * RSB + kb32);

            uint32_t br[NFR][2];
#pragma unroll
            for (int fp = 0; fp < NLD; fp++) {
                uint32_t r0, r1, r2, r3;
                LDSM_X4(r0, r1, r2, r3,
                        smA + B_HI_OFF + b_off + fp * 16 * RSB + kb32);
                br[2 * fp][0] = r0; br[2 * fp][1] = r2;
                br[2 * fp + 1][0] = r1; br[2 * fp + 1][1] = r3;
            }
#pragma unroll
            for (int fm = 0; fm < 4; fm++)
#pragma unroll
                for (int fn = 0; fn < NFR; fn++)
                    MMA16816(acc[fm][fn], ah[fm], br[fn]);
#pragma unroll
            for (int fm = 0; fm < 4; fm++)
#pragma unroll
                for (int fn = 0; fn < NFR; fn++)
                    MMA16816(acc[fm][fn], al[fm], br[fn]);
#pragma unroll
            for (int fp = 0; fp < NLD; fp++) {
                uint32_t r0, r1, r2, r3;
                LDSM_X4(r0, r1, r2, r3,
                        smA + B_LO_OFF + b_off + fp * 16 * RSB + kb32);
                br[2 * fp][0] = r0; br[2 * fp][1] = r2;
                br[2 * fp + 1][0] = r1; br[2 * fp + 1][1] = r3;
            }
#pragma unroll
            for (int fm = 0; fm < 4; fm++)
#pragma unroll
                for (int fn = 0; fn < NFR; fn++)
                    MMA16816(acc[fm][fn], ah[fm], br[fn]);
        }
    }

    // epilogue: gelu -> tf32-rounded fp32
    int gr = lane >> 2;
    int qc = (lane & 3) * 2;
#pragma unroll
    for (int fm = 0; fm < 4; fm++) {
        int m0 = bm + warp_m * 64 + fm * 16 + gr;
#pragma unroll
        for (int fn = 0; fn < NFR; fn++) {
            int c0 = bn + warp_n * (BN_ / 4) + fn * 8 + qc;
            float2 bv = *reinterpret_cast<const float2*>(bias + c0);
            float g00 = gelu_exact(acc[fm][fn][0] + bv.x);
            float g01 = gelu_exact(acc[fm][fn][1] + bv.y);
            float g10 = gelu_exact(acc[fm][fn][2] + bv.x);
            float g11 = gelu_exact(acc[fm][fn][3] + bv.y);
            float2 w0 = make_float2(__uint_as_float(tf32r(g00)), __uint_as_float(tf32r(g01)));
            float2 w1 = make_float2(__uint_as_float(tf32r(g10)), __uint_as_float(tf32r(g11)));
            *reinterpret_cast<float2*>(outf + (size_t)m0 * N + c0) = w0;
            *reinterpret_cast<float2*>(outf + (size_t)(m0 + 8) * N + c0) = w1;
        }
    }
}

// ---------------------------------------------------------------------------
// GEMM2 (tf32): logits = h @ W2^T + b2.  M=8192, N=32000, K=256.
// BM=128, BN=256, BK=32, 512 threads (16 warps 4x4), warp tile 32x64.
// Smem rows stride 144B -> conflict-free tf32 fragment loads.
// ---------------------------------------------------------------------------
#define NTH2 512
#define RS2  144                          // 32 f32 (128B) + 16B pad
#define ROWS2 (128 + 256)                 // A rows + B rows per stage
#define STAGE2 (ROWS2 * RS2)              // 55296
#define SMEM2 (3 * STAGE2)                // 165888
#define B_OFF2 (128 * RS2)

__global__ void __launch_bounds__(NTH2, 1)
gemm_tf32(const float* __restrict__ A, const float* __restrict__ Bt,
          const float* __restrict__ bias, float* __restrict__ out) {
    extern __shared__ char smem[];
    constexpr int KD = HIDDEN;            // 256
    constexpr int NKB = KD / 32;          // 8
    uint32_t sb = smem_u32(smem);
    int tid = threadIdx.x;
    int wid = tid >> 5;
    int lane = tid & 31;
    int warp_m = wid & 3;                 // 0..3 (32 rows each)
    int warp_n = wid >> 2;                // 0..3 (64 cols each)
    int bm = blockIdx.x * 128;            // x = M-tiles (A stays L2-resident)
    int bn = blockIdx.y * 256;

    float acc[2][8][4];
#pragma unroll
    for (int i = 0; i < 2; i++)
#pragma unroll
        for (int j = 0; j < 8; j++)
#pragma unroll
            for (int r = 0; r < 4; r++) acc[i][j][r] = 0.0f;

    auto issue = [&](int kb) {
        int s = kb % 3;
        int k0 = kb * 32;
        uint32_t base = sb + s * STAGE2;
#pragma unroll
        for (int i = 0; i < 6; i++) {
            int li = tid + i * NTH2;       // 0..3071
            int r = li >> 3;
            int ch = li & 7;
            const float* src = (r < 128)
                ? A  + (size_t)(bm + r) * KD + k0 + ch * 4
                : Bt + (size_t)(bn + r - 128) * KD + k0 + ch * 4;
            cp16(base + r * RS2 + ch * 16, src);
        }
        cp_commit();
    };

    issue(0);
    issue(1);

    int g = lane >> 2;                    // 0..7
    int c = lane & 3;                     // 0..3
    uint32_t a_base = (uint32_t)(warp_m * 32 + g) * RS2 + c * 4;
    uint32_t b_base = B_OFF2 + (uint32_t)(warp_n * 64 + g) * RS2 + c * 4;

    for (int kb = 0; kb < NKB; kb++) {
        int s = kb % 3;
        asm volatile("cp.async.wait_group 1;\n" ::: "memory");
        __syncthreads();
        if (kb + 2 < NKB) issue(kb + 2);

        uint32_t smA = sb + s * STAGE2;
#pragma unroll
        for (int k8 = 0; k8 < 4; k8++) {
            uint32_t ko = k8 * 32;        // 8 f32 = 32B per k8 step
            uint32_t ar[2][4];
#pragma unroll
            for (int mf = 0; mf < 2; mf++) {
                uint32_t ad = smA + a_base + mf * 16 * RS2 + ko;
                ar[mf][0] = lds32(ad);
                ar[mf][1] = lds32(ad + 8 * RS2);
                ar[mf][2] = lds32(ad + 16);
                ar[mf][3] = lds32(ad + 8 * RS2 + 16);
            }
#pragma unroll
            for (int fn = 0; fn < 8; fn++) {
                uint32_t bd = smA + b_base + fn * 8 * RS2 + ko;
                uint32_t br[2];
                br[0] = lds32(bd);
                br[1] = lds32(bd + 16);
#pragma unroll
                for (int mf = 0; mf < 2; mf++)
                    MMATF32(acc[mf][fn], ar[mf], br);
            }
        }
    }

    // epilogue
    int qc = c * 2;
#pragma unroll
    for (int mf = 0; mf < 2; mf++) {
        int m0 = bm + warp_m * 32 + mf * 16 + g;
#pragma unroll
        for (int fn = 0; fn < 8; fn++) {
            int c0 = bn + warp_n * 64 + fn * 8 + qc;
            float2 bv = *reinterpret_cast<const float2*>(bias + c0);
            *reinterpret_cast<float2*>(out + (size_t)m0 * VOCAB + c0) =
                make_float2(acc[mf][fn][0] + bv.x, acc[mf][fn][1] + bv.y);
            *reinterpret_cast<float2*>(out + (size_t)(m0 + 8) * VOCAB + c0) =
                make_float2(acc[mf][fn][2] + bv.x, acc[mf][fn][3] + bv.y);
        }
    }
}

// ---------------------------------------------------------------------------
extern "C" void kernel_launch(void* const* d_in, const int* in_sizes, int n_in,
                              void* d_out, int out_size) {
    const int*   tokens = (const int*)  d_in[0];
    const float* emb    = (const float*)d_in[1];
    const float* W1     = (const float*)d_in[2];
    const float* b1     = (const float*)d_in[3];
    const float* W2     = (const float*)d_in[4];
    const float* b2     = (const float*)d_in[5];
    float* out = (float*)d_out;

    __nv_bfloat16 *fh, *fl, *w1h, *w1l;
    float *w2t, *hp;
    cudaGetSymbolAddress((void**)&fh,  g_flat_hi);
    cudaGetSymbolAddress((void**)&fl,  g_flat_lo);
    cudaGetSymbolAddress((void**)&w1h, g_w1t_hi);
    cudaGetSymbolAddress((void**)&w1l, g_w1t_lo);
    cudaGetSymbolAddress((void**)&w2t, g_w2t);
    cudaGetSymbolAddress((void**)&hp,  g_h);

    constexpr int SMEM1 = 3 * (256 + 2 * 128) * RSB;   // 122880
    cudaFuncSetAttribute(gemm_hmma<K1, 128>,
                         cudaFuncAttributeMaxDynamicSharedMemorySize, SMEM1);
    cudaFuncSetAttribute(gemm_tf32,
                         cudaFuncAttributeMaxDynamicSharedMemorySize, SMEM2);

    // 1) gather + split (bf16 hi/lo)
    {
        int total4 = MROWS * (K1 / 4);
        gather_split<<<(total4 + 255) / 256, 256>>>(tokens, emb);
    }
    // 2) weight prep
    {
        dim3 blk(32, 32);
        transpose_split<<<dim3(HIDDEN / 32, K1 / 32), blk>>>(W1, w1h, w1l, K1, HIDDEN);
        transpose_tf32<<<dim3(VOCAB / 32, HIDDEN / 32), blk>>>(W2, w2t, HIDDEN, VOCAB);
    }
    // 3) h = tf32(gelu(flat @ W1 + b1))   (M=8192, N=256, K=1536)
    {
        dim3 grid(HIDDEN / 128, MROWS / 128);   // (2, 64)
        gemm_hmma<K1, 128><<<grid, NTH, SMEM1>>>(fh, fl, w1h, w1l, b1, hp, HIDDEN);
    }
    // 4) logits = h @ W2 + b2   (M=8192, N=32000, K=256), tf32
    {
        dim3 grid(MROWS / 128, VOCAB / 256);    // (64, 125)
        gemm_tf32<<<grid, NTH2, SMEM2>>>(hp, w2t, b2, out);
    }
}

// round 6
// speedup vs baseline: 4.0650x; 1.6005x over previous
#include <cuda_runtime.h>
#include <cuda_bf16.h>
#include <cuda_fp16.h>
#include <math.h>
#include <stdint.h>

#define SEQ    2048
#define BATCH  4
#define KCTX   3
#define EMBED  512
#define HIDDEN 256
#define VOCAB  32000
#define MROWS  (SEQ * BATCH)      // 8192
#define K1     (KCTX * EMBED)     // 1536

// ---------------- scratch (static device globals) ----------------
__device__ __nv_bfloat16 g_flat_hi[MROWS * K1];
__device__ __nv_bfloat16 g_flat_lo[MROWS * K1];
__device__ __nv_bfloat16 g_w1t_hi[HIDDEN * K1];     // [256][1536] K-major
__device__ __nv_bfloat16 g_w1t_lo[HIDDEN * K1];
__device__ __half        g_w2t[VOCAB * HIDDEN];     // [32000][256] K-major fp16
__device__ __half        g_h[MROWS * HIDDEN];       // [8192][256] fp16

// ---------------- helpers ----------------
__device__ __forceinline__ uint32_t smem_u32(const void* p) {
    uint32_t a;
    asm("{ .reg .u64 t; cvta.to.shared.u64 t, %1; cvt.u32.u64 %0, t; }" : "=r"(a) : "l"(p));
    return a;
}
__device__ __forceinline__ void cp16(uint32_t dst, const void* src) {
    asm volatile("cp.async.cg.shared.global [%0], [%1], 16;\n" :: "r"(dst), "l"(src));
}
__device__ __forceinline__ void cp_commit() { asm volatile("cp.async.commit_group;\n" ::: "memory"); }

#define LDSM_X4(r0, r1, r2, r3, addr) \
    asm volatile("ldmatrix.sync.aligned.m8n8.x4.shared.b16 {%0,%1,%2,%3}, [%4];" \
                 : "=r"(r0), "=r"(r1), "=r"(r2), "=r"(r3) : "r"(addr))

#define MMA_BF16(d, a, b) \
    asm volatile("mma.sync.aligned.m16n8k16.row.col.f32.bf16.bf16.f32 " \
                 "{%0,%1,%2,%3}, {%4,%5,%6,%7}, {%8,%9}, {%0,%1,%2,%3};" \
                 : "+f"((d)[0]), "+f"((d)[1]), "+f"((d)[2]), "+f"((d)[3]) \
                 : "r"((a)[0]), "r"((a)[1]), "r"((a)[2]), "r"((a)[3]), \
                   "r"((b)[0]), "r"((b)[1]))

#define MMA_F16(d, a, b) \
    asm volatile("mma.sync.aligned.m16n8k16.row.col.f32.f16.f16.f32 " \
                 "{%0,%1,%2,%3}, {%4,%5,%6,%7}, {%8,%9}, {%0,%1,%2,%3};" \
                 : "+f"((d)[0]), "+f"((d)[1]), "+f"((d)[2]), "+f"((d)[3]) \
                 : "r"((a)[0]), "r"((a)[1]), "r"((a)[2]), "r"((a)[3]), \
                   "r"((b)[0]), "r"((b)[1]))

__device__ __forceinline__ void bsplit(float x, __nv_bfloat16& hi, __nv_bfloat16& lo) {
    hi = __float2bfloat16(x);
    lo = __float2bfloat16(x - __bfloat162float(hi));
}
__device__ __forceinline__ float gelu_exact(float x) {
    return 0.5f * x * (1.0f + erff(x * 0.70710678118654752f));
}

// ---------------------------------------------------------------------------
// Gather + split (bf16 hi/lo for GEMM1)
// ---------------------------------------------------------------------------
__global__ void gather_split(const int* __restrict__ tokens, const float* __restrict__ emb) {
    int idx = blockIdx.x * blockDim.x + threadIdx.x;  // one float4
    const int Q = K1 / 4;
    if (idx >= MROWS * Q) return;
    int r = idx / Q;
    int q = idx - r * Q;
    int s = r >> 2;
    int b = r & 3;
    int g = q / (EMBED / 4);
    int e4 = q - g * (EMBED / 4);
    int pos = s + g - (KCTX - 1);
    int tok = (pos >= 0) ? tokens[pos * BATCH + b] : 0;
    float4 v = reinterpret_cast<const float4*>(emb + (size_t)tok * EMBED)[e4];
    size_t off = (size_t)r * K1 + g * EMBED + e4 * 4;
    __nv_bfloat16 h0, h1, h2, h3, l0, l1, l2, l3;
    bsplit(v.x, h0, l0); bsplit(v.y, h1, l1); bsplit(v.z, h2, l2); bsplit(v.w, h3, l3);
    *reinterpret_cast<__nv_bfloat162*>(g_flat_hi + off)     = __nv_bfloat162(h0, h1);
    *reinterpret_cast<__nv_bfloat162*>(g_flat_hi + off + 2) = __nv_bfloat162(h2, h3);
    *reinterpret_cast<__nv_bfloat162*>(g_flat_lo + off)     = __nv_bfloat162(l0, l1);
    *reinterpret_cast<__nv_bfloat162*>(g_flat_lo + off + 2) = __nv_bfloat162(l2, l3);
}

// ---------------------------------------------------------------------------
// Transpose + split (bf16 hi/lo) for W1
// ---------------------------------------------------------------------------
__global__ void transpose_split(const float* __restrict__ W,
                                __nv_bfloat16* __restrict__ Thi,
                                __nv_bfloat16* __restrict__ Tlo, int R, int C) {
    __shared__ float t[32][33];
    int c = blockIdx.x * 32 + threadIdx.x;
    int r = blockIdx.y * 32 + threadIdx.y;
    t[threadIdx.y][threadIdx.x] = W[(size_t)r * C + c];
    __syncthreads();
    int c2 = blockIdx.x * 32 + threadIdx.y;
    int r2 = blockIdx.y * 32 + threadIdx.x;
    float v = t[threadIdx.x][threadIdx.y];
    __nv_bfloat16 h, l;
    bsplit(v, h, l);
    Thi[(size_t)c2 * R + r2] = h;
    Tlo[(size_t)c2 * R + r2] = l;
}

// ---------------------------------------------------------------------------
// Transpose + fp16 for W2: W[R][C] -> T[C][R]
// ---------------------------------------------------------------------------
__global__ void transpose_f16(const float* __restrict__ W, __half* __restrict__ T,
                              int R, int C) {
    __shared__ float t[32][33];
    int c = blockIdx.x * 32 + threadIdx.x;
    int r = blockIdx.y * 32 + threadIdx.y;
    t[threadIdx.y][threadIdx.x] = W[(size_t)r * C + c];
    __syncthreads();
    int c2 = blockIdx.x * 32 + threadIdx.y;
    int r2 = blockIdx.y * 32 + threadIdx.x;
    T[(size_t)c2 * R + r2] = __float2half_rn(t[threadIdx.x][threadIdx.y]);
}

// ---------------------------------------------------------------------------
// GEMM1 (HMMA split-bf16, fused 3-phase): h = fp16(gelu(flat @ W1^T + b1))
// BM=128, BN=128, BK=32, 8 warps (2x4), warp tile 64x32.
// ---------------------------------------------------------------------------
#define NTH 256
#define RSB 80   // 32 x 16-bit (64B) + 16B pad

template <int KD, int BN_>
__global__ void __launch_bounds__(NTH, 1)
gemm_hmma(const __nv_bfloat16* __restrict__ Ahi, const __nv_bfloat16* __restrict__ Alo,
          const __nv_bfloat16* __restrict__ Bhi, const __nv_bfloat16* __restrict__ Blo,
          const float* __restrict__ bias, __half* __restrict__ outh, int N) {
    extern __shared__ char smem[];
    constexpr int NKB = KD / 32;
    constexpr int NFR = BN_ / 32;
    constexpr int NLD = NFR / 2;
    constexpr int ROWS_STAGE = 256 + 2 * BN_;
    constexpr int STAGE_B = ROWS_STAGE * RSB;
    constexpr int NI = ROWS_STAGE / 64;
    constexpr uint32_t A_LO_OFF = 128 * RSB;
    constexpr uint32_t B_HI_OFF = 256 * RSB;
    constexpr uint32_t B_LO_OFF = (256 + BN_) * RSB;

    uint32_t sb = smem_u32(smem);
    int tid = threadIdx.x;
    int wid = tid >> 5;
    int lane = tid & 31;
    int warp_m = wid & 1;
    int warp_n = wid >> 1;
    int bm = blockIdx.y * 128;
    int bn = blockIdx.x * BN_;

    float acc[4][NFR][4];
#pragma unroll
    for (int i = 0; i < 4; i++)
#pragma unroll
        for (int j = 0; j < NFR; j++)
#pragma unroll
            for (int r = 0; r < 4; r++) acc[i][j][r] = 0.0f;

    auto issue = [&](int kb) {
        int s = kb % 3;
        int koff = kb * 32;
        uint32_t base = sb + s * STAGE_B;
#pragma unroll
        for (int i = 0; i < NI; i++) {
            int li = tid + i * NTH;
            int r = li >> 2;
            int ch = li & 3;
            const __nv_bfloat16* src;
            if (i < 2)       src = Ahi + (size_t)(bm + r) * KD;
            else if (i < 4)  src = Alo + (size_t)(bm + r - 128) * KD;
            else if (i < 4 + BN_ / 64)
                             src = Bhi + (size_t)(bn + r - 256) * KD;
            else             src = Blo + (size_t)(bn + r - 256 - BN_) * KD;
            cp16(base + r * RSB + ch * 16, src + koff + ch * 8);
        }
        cp_commit();
    };

    issue(0);
    issue(1);

    int lrow = (lane & 7) + ((lane >> 3) & 1) * 8;
    int lkb = (lane >> 4) * 16;
    uint32_t a_off = (uint32_t)(warp_m * 64 + lrow) * RSB + lkb;
    uint32_t b_off = (uint32_t)(warp_n * (BN_ / 4) + lrow) * RSB + lkb;

    for (int kb = 0; kb < NKB; kb++) {
        int s = kb % 3;
        asm volatile("cp.async.wait_group 1;\n" ::: "memory");
        __syncthreads();
        if (kb + 2 < NKB) issue(kb + 2);

        uint32_t smA = sb + s * STAGE_B;
#pragma unroll
        for (int k16 = 0; k16 < 2; k16++) {
            uint32_t kb32 = k16 * 32;
            uint32_t ah[4][4], al[4][4];
#pragma unroll
            for (int fm = 0; fm < 4; fm++)
                LDSM_X4(ah[fm][0], ah[fm][1], ah[fm][2], ah[fm][3],
                        smA + a_off + fm * 16 * RSB + kb32);
#pragma unroll
            for (int fm = 0; fm < 4; fm++)
                LDSM_X4(al[fm][0], al[fm][1], al[fm][2], al[fm][3],
                        smA + A_LO_OFF + a_off + fm * 16 * RSB + kb32);

            uint32_t br[NFR][2];
#pragma unroll
            for (int fp = 0; fp < NLD; fp++) {
                uint32_t r0, r1, r2, r3;
                LDSM_X4(r0, r1, r2, r3,
                        smA + B_HI_OFF + b_off + fp * 16 * RSB + kb32);
                br[2 * fp][0] = r0; br[2 * fp][1] = r2;
                br[2 * fp + 1][0] = r1; br[2 * fp + 1][1] = r3;
            }
#pragma unroll
            for (int fm = 0; fm < 4; fm++)
#pragma unroll
                for (int fn = 0; fn < NFR; fn++)
                    MMA_BF16(acc[fm][fn], ah[fm], br[fn]);
#pragma unroll
            for (int fm = 0; fm < 4; fm++)
#pragma unroll
                for (int fn = 0; fn < NFR; fn++)
                    MMA_BF16(acc[fm][fn], al[fm], br[fn]);
#pragma unroll
            for (int fp = 0; fp < NLD; fp++) {
                uint32_t r0, r1, r2, r3;
                LDSM_X4(r0, r1, r2, r3,
                        smA + B_LO_OFF + b_off + fp * 16 * RSB + kb32);
                br[2 * fp][0] = r0; br[2 * fp][1] = r2;
                br[2 * fp + 1][0] = r1; br[2 * fp + 1][1] = r3;
            }
#pragma unroll
            for (int fm = 0; fm < 4; fm++)
#pragma unroll
                for (int fn = 0; fn < NFR; fn++)
                    MMA_BF16(acc[fm][fn], ah[fm], br[fn]);
        }
    }

    // epilogue: gelu -> fp16
    int gr = lane >> 2;
    int qc = (lane & 3) * 2;
#pragma unroll
    for (int fm = 0; fm < 4; fm++) {
        int m0 = bm + warp_m * 64 + fm * 16 + gr;
#pragma unroll
        for (int fn = 0; fn < NFR; fn++) {
            int c0 = bn + warp_n * (BN_ / 4) + fn * 8 + qc;
            float2 bv = *reinterpret_cast<const float2*>(bias + c0);
            float g00 = gelu_exact(acc[fm][fn][0] + bv.x);
            float g01 = gelu_exact(acc[fm][fn][1] + bv.y);
            float g10 = gelu_exact(acc[fm][fn][2] + bv.x);
            float g11 = gelu_exact(acc[fm][fn][3] + bv.y);
            *reinterpret_cast<__half2*>(outh + (size_t)m0 * N + c0) =
                __floats2half2_rn(g00, g01);
            *reinterpret_cast<__half2*>(outh + (size_t)(m0 + 8) * N + c0) =
                __floats2half2_rn(g10, g11);
        }
    }
}

// ---------------------------------------------------------------------------
// GEMM2 (fp16 single-phase): logits = h @ W2^T + b2.  M=8192, N=32000, K=256.
// BM=128, BN=256, BK=32, 512 threads (16 warps 4x4), warp tile 32x64.
// ---------------------------------------------------------------------------
#define NTH2 512
#define ROWS2 (128 + 256)
#define STAGE2 (ROWS2 * RSB)              // 30720
#define SMEM2 (3 * STAGE2)                // 92160
#define B_OFF2 (128 * RSB)

__global__ void __launch_bounds__(NTH2, 1)
gemm_f16(const __half* __restrict__ A, const __half* __restrict__ Bt,
         const float* __restrict__ bias, float* __restrict__ out) {
    extern __shared__ char smem[];
    constexpr int KD = HIDDEN;            // 256
    constexpr int NKB = KD / 32;          // 8
    uint32_t sb = smem_u32(smem);
    int tid = threadIdx.x;
    int wid = tid >> 5;
    int lane = tid & 31;
    int warp_m = wid & 3;                 // 0..3 (32 rows)
    int warp_n = wid >> 2;                // 0..3 (64 cols)
    int bm = blockIdx.x * 128;
    int bn = blockIdx.y * 256;

    float acc[2][8][4];
#pragma unroll
    for (int i = 0; i < 2; i++)
#pragma unroll
        for (int j = 0; j < 8; j++)
#pragma unroll
            for (int r = 0; r < 4; r++) acc[i][j][r] = 0.0f;

    auto issue = [&](int kb) {
        int s = kb % 3;
        int k0 = kb * 32;
        uint32_t base = sb + s * STAGE2;
#pragma unroll
        for (int i = 0; i < 3; i++) {
            int li = tid + i * NTH2;       // 0..1535
            int r = li >> 2;               // 0..383
            int ch = li & 3;
            const __half* src = (r < 128)
                ? A  + (size_t)(bm + r) * KD + k0 + ch * 8
                : Bt + (size_t)(bn + r - 128) * KD + k0 + ch * 8;
            cp16(base + r * RSB + ch * 16, src);
        }
        cp_commit();
    };

    issue(0);
    issue(1);

    int lrow = (lane & 7) + ((lane >> 3) & 1) * 8;
    int lkb = (lane >> 4) * 16;
    uint32_t a_off = (uint32_t)(warp_m * 32 + lrow) * RSB + lkb;
    uint32_t b_off = B_OFF2 + (uint32_t)(warp_n * 64 + lrow) * RSB + lkb;

    for (int kb = 0; kb < NKB; kb++) {
        int s = kb % 3;
        asm volatile("cp.async.wait_group 1;\n" ::: "memory");
        __syncthreads();
        if (kb + 2 < NKB) issue(kb + 2);

        uint32_t smA = sb + s * STAGE2;
#pragma unroll
        for (int k16 = 0; k16 < 2; k16++) {
            uint32_t kb32 = k16 * 32;
            uint32_t ar[2][4];
#pragma unroll
            for (int fm = 0; fm < 2; fm++)
                LDSM_X4(ar[fm][0], ar[fm][1], ar[fm][2], ar[fm][3],
                        smA + a_off + fm * 16 * RSB + kb32);
            uint32_t br[8][2];
#pragma unroll
            for (int fp = 0; fp < 4; fp++) {
                uint32_t r0, r1, r2, r3;
                LDSM_X4(r0, r1, r2, r3,
                        smA + b_off + fp * 16 * RSB + kb32);
                br[2 * fp][0] = r0; br[2 * fp][1] = r2;
                br[2 * fp + 1][0] = r1; br[2 * fp + 1][1] = r3;
            }
#pragma unroll
            for (int fm = 0; fm < 2; fm++)
#pragma unroll
                for (int fn = 0; fn < 8; fn++)
                    MMA_F16(acc[fm][fn], ar[fm], br[fn]);
        }
    }

    // epilogue
    int gr = lane >> 2;
    int qc = (lane & 3) * 2;
#pragma unroll
    for (int fm = 0; fm < 2; fm++) {
        int m0 = bm + warp_m * 32 + fm * 16 + gr;
#pragma unroll
        for (int fn = 0; fn < 8; fn++) {
            int c0 = bn + warp_n * 64 + fn * 8 + qc;
            float2 bv = *reinterpret_cast<const float2*>(bias + c0);
            *reinterpret_cast<float2*>(out + (size_t)m0 * VOCAB + c0) =
                make_float2(acc[fm][fn][0] + bv.x, acc[fm][fn][1] + bv.y);
            *reinterpret_cast<float2*>(out + (size_t)(m0 + 8) * VOCAB + c0) =
                make_float2(acc[fm][fn][2] + bv.x, acc[fm][fn][3] + bv.y);
        }
    }
}

// ---------------------------------------------------------------------------
extern "C" void kernel_launch(void* const* d_in, const int* in_sizes, int n_in,
                              void* d_out, int out_size) {
    const int*   tokens = (const int*)  d_in[0];
    const float* emb    = (const float*)d_in[1];
    const float* W1     = (const float*)d_in[2];
    const float* b1     = (const float*)d_in[3];
    const float* W2     = (const float*)d_in[4];
    const float* b2     = (const float*)d_in[5];
    float* out = (float*)d_out;

    __nv_bfloat16 *fh, *fl, *w1h, *w1l;
    __half *w2t, *hp;
    cudaGetSymbolAddress((void**)&fh,  g_flat_hi);
    cudaGetSymbolAddress((void**)&fl,  g_flat_lo);
    cudaGetSymbolAddress((void**)&w1h, g_w1t_hi);
    cudaGetSymbolAddress((void**)&w1l, g_w1t_lo);
    cudaGetSymbolAddress((void**)&w2t, g_w2t);
    cudaGetSymbolAddress((void**)&hp,  g_h);

    constexpr int SMEM1 = 3 * (256 + 2 * 128) * RSB;   // 122880
    cudaFuncSetAttribute(gemm_hmma<K1, 128>,
                         cudaFuncAttributeMaxDynamicSharedMemorySize, SMEM1);
    cudaFuncSetAttribute(gemm_f16,
                         cudaFuncAttributeMaxDynamicSharedMemorySize, SMEM2);

    // 1) gather + split (bf16 hi/lo)
    {
        int total4 = MROWS * (K1 / 4);
        gather_split<<<(total4 + 255) / 256, 256>>>(tokens, emb);
    }
    // 2) weight prep
    {
        dim3 blk(32, 32);
        transpose_split<<<dim3(HIDDEN / 32, K1 / 32), blk>>>(W1, w1h, w1l, K1, HIDDEN);
        transpose_f16<<<dim3(VOCAB / 32, HIDDEN / 32), blk>>>(W2, w2t, HIDDEN, VOCAB);
    }
    // 3) h = fp16(gelu(flat @ W1 + b1))   (M=8192, N=256, K=1536)
    {
        dim3 grid(HIDDEN / 128, MROWS / 128);   // (2, 64)
        gemm_hmma<K1, 128><<<grid, NTH, SMEM1>>>(fh, fl, w1h, w1l, b1, hp, HIDDEN);
    }
    // 4) logits = h @ W2 + b2   (M=8192, N=32000, K=256), fp16 HMMA
    {
        dim3 grid(MROWS / 128, VOCAB / 256);    // (64, 125)
        gemm_f16<<<grid, NTH2, SMEM2>>>(hp, w2t, b2, out);
    }
}